// round 1
// baseline (speedup 1.0000x reference)
#include <cuda_runtime.h>
#include <math.h>

// Problem constants
#define NN 50000
#define NE 800000
#define IN_DIM 128
#define HID 32
#define HEADS 8
#define F1DIM 256    // HEADS*HID
#define ODIM 64
#define NEG 0.2f
#define ENC_NEG_INF 0x007FFFFFu   // enc(-inf)

// ---------------- scratch (device globals; no allocation) ----------------
__device__ alignas(16) float g_f1[(size_t)NN * F1DIM];   // 51.2 MB
__device__ alignas(16) float g_h [(size_t)NN * F1DIM];   // 51.2 MB (agg1 -> elu in place)
__device__ alignas(16) float g_f2[(size_t)NN * ODIM];    // 12.8 MB
__device__ float    g_el1[NN * HEADS];
__device__ float    g_er1[NN * HEADS];
__device__ unsigned g_m1 [NN * HEADS];
__device__ float    g_mf1[NN * HEADS];
__device__ float    g_s1 [NN * HEADS];
__device__ float    g_a1 [(size_t)NE * HEADS];           // 25.6 MB
__device__ float    g_el2[NN];
__device__ float    g_er2[NN];
__device__ unsigned g_m2 [NN];
__device__ float    g_mf2[NN];
__device__ float    g_s2 [NN];
__device__ float    g_a2 [NE];

// order-preserving float <-> uint encoding for atomicMax
__device__ __forceinline__ unsigned enc_f(float f) {
    unsigned u = __float_as_uint(f);
    return (u & 0x80000000u) ? ~u : (u | 0x80000000u);
}
__device__ __forceinline__ float dec_f(unsigned u) {
    return (u & 0x80000000u) ? __uint_as_float(u ^ 0x80000000u)
                             : __uint_as_float(~u);
}
__device__ __forceinline__ float lrelu(float x) { return x >= 0.f ? x : NEG * x; }

__device__ __forceinline__ void red_add_f4(float* p, float4 v) {
    asm volatile("red.global.add.v4.f32 [%0], {%1,%2,%3,%4};"
                 :: "l"(p), "f"(v.x), "f"(v.y), "f"(v.z), "f"(v.w) : "memory");
}

// ---------------- GEMM: C[M,N] = A[M,K] @ B[K,N], row-major ----------------
template<int BM, int BN, int BK, int TM, int TN>
__global__ void gemm_kernel(const float* __restrict__ A, const float* __restrict__ B,
                            float* __restrict__ C, int M, int N, int K) {
    __shared__ float As[BK][BM];
    __shared__ float Bs[BK][BN];
    const int NT = (BM / TM) * (BN / TN);
    const int tid  = threadIdx.x;
    const int tcol = tid % (BN / TN);
    const int trow = tid / (BN / TN);
    const int rowBase = blockIdx.y * BM;
    const int colBase = blockIdx.x * BN;

    float acc[TM][TN];
#pragma unroll
    for (int i = 0; i < TM; i++)
#pragma unroll
        for (int j = 0; j < TN; j++) acc[i][j] = 0.f;

    for (int k0 = 0; k0 < K; k0 += BK) {
        for (int i = tid; i < BM * BK; i += NT) {
            int r = i / BK, c = i % BK;
            int gr = rowBase + r;
            As[c][r] = (gr < M) ? A[(size_t)gr * K + k0 + c] : 0.f;
        }
        for (int i = tid; i < BK * BN; i += NT) {
            int r = i / BN, c = i % BN;
            Bs[r][c] = B[(size_t)(k0 + r) * N + colBase + c];
        }
        __syncthreads();
#pragma unroll
        for (int k = 0; k < BK; k++) {
            float a[TM], b[TN];
#pragma unroll
            for (int i = 0; i < TM; i++) a[i] = As[k][trow * TM + i];
#pragma unroll
            for (int j = 0; j < TN; j++) b[j] = Bs[k][tcol * TN + j];
#pragma unroll
            for (int i = 0; i < TM; i++)
#pragma unroll
                for (int j = 0; j < TN; j++) acc[i][j] += a[i] * b[j];
        }
        __syncthreads();
    }
#pragma unroll
    for (int i = 0; i < TM; i++) {
        int gr = rowBase + trow * TM + i;
        if (gr >= M) continue;
#pragma unroll
        for (int j = 0; j < TN; j++)
            C[(size_t)gr * N + colBase + tcol * TN + j] = acc[i][j];
    }
}

// ---------------- per-node attention halves ----------------
__global__ void attn_lr1(const float* __restrict__ al, const float* __restrict__ ar) {
    int i = blockIdx.x * blockDim.x + threadIdx.x;   // over NN*HEADS
    if (i >= NN * HEADS) return;
    int h = i & (HEADS - 1);
    const float* fp = g_f1 + (size_t)(i >> 3) * F1DIM + h * HID;
    float sl = 0.f, sr = 0.f;
#pragma unroll
    for (int d = 0; d < HID; d++) {
        float v = fp[d];
        sl += v * al[h * HID + d];
        sr += v * ar[h * HID + d];
    }
    g_el1[i] = sl;
    g_er1[i] = sr;
}

__global__ void attn_lr2(const float* __restrict__ al, const float* __restrict__ ar) {
    int i = blockIdx.x * blockDim.x + threadIdx.x;   // over NN
    if (i >= NN) return;
    const float* fp = g_f2 + (size_t)i * ODIM;
    float sl = 0.f, sr = 0.f;
#pragma unroll
    for (int d = 0; d < ODIM; d++) {
        float v = fp[d];
        sl += v * al[d];
        sr += v * ar[d];
    }
    g_el2[i] = sl;
    g_er2[i] = sr;
}

// ---------------- init ----------------
__global__ void init1() {
    int i = blockIdx.x * blockDim.x + threadIdx.x;   // over NN*F1DIM
    if (i < NN * F1DIM) g_h[i] = 0.f;
    if (i < NN * HEADS) { g_m1[i] = ENC_NEG_INF; g_s1[i] = 0.f; }
}
__global__ void init2(float* __restrict__ out) {
    int i = blockIdx.x * blockDim.x + threadIdx.x;   // over NN*ODIM
    if (i < NN * ODIM) out[i] = 0.f;
    if (i < NN) { g_m2[i] = ENC_NEG_INF; g_s2[i] = 0.f; }
}

// ---------------- layer-1 edge passes ----------------
__global__ void edge_max1(const int* __restrict__ src, const int* __restrict__ dst) {
    int idx = blockIdx.x * blockDim.x + threadIdx.x;  // over NE*HEADS
    if (idx >= NE * HEADS) return;
    int e = idx >> 3, h = idx & 7;
    int s = src[e], d = dst[e];
    float v = lrelu(g_el1[s * HEADS + h] + g_er1[d * HEADS + h]);
    atomicMax(&g_m1[d * HEADS + h], enc_f(v));
}
__global__ void fix_m1() {
    int i = blockIdx.x * blockDim.x + threadIdx.x;
    if (i >= NN * HEADS) return;
    float f = dec_f(g_m1[i]);
    g_mf1[i] = isfinite(f) ? f : 0.f;
}
__global__ void edge_sum1(const int* __restrict__ src, const int* __restrict__ dst) {
    int idx = blockIdx.x * blockDim.x + threadIdx.x;  // over NE*HEADS
    if (idx >= NE * HEADS) return;
    int e = idx >> 3, h = idx & 7;
    int s = src[e], d = dst[e];
    float v = lrelu(g_el1[s * HEADS + h] + g_er1[d * HEADS + h]);
    float a = expf(v - g_mf1[d * HEADS + h]);
    g_a1[(size_t)e * HEADS + h] = a;
    atomicAdd(&g_s1[d * HEADS + h], a);
}
__global__ void inv_s1() {
    int i = blockIdx.x * blockDim.x + threadIdx.x;
    if (i >= NN * HEADS) return;
    float s = g_s1[i];
    g_s1[i] = 1.f / (s > 0.f ? s : 1.f);
}
__global__ void edge_msg1(const int* __restrict__ src, const int* __restrict__ dst) {
    int idx = blockIdx.x * blockDim.x + threadIdx.x;  // over NE*64
    if (idx >= NE * 64) return;
    int e = idx >> 6, h = (idx >> 3) & 7, q = idx & 7;
    int s = src[e], d = dst[e];
    float alpha = g_a1[(size_t)e * HEADS + h] * g_s1[d * HEADS + h];
    const float4 f = *(const float4*)&g_f1[(size_t)s * F1DIM + h * HID + q * 4];
    red_add_f4(&g_h[(size_t)d * F1DIM + h * HID + q * 4],
               make_float4(f.x * alpha, f.y * alpha, f.z * alpha, f.w * alpha));
}

// ELU(x + b1) in place on g_h
__global__ void elu_bias1(const float* __restrict__ b1) {
    int i = blockIdx.x * blockDim.x + threadIdx.x;   // over NN*F1DIM
    if (i >= NN * F1DIM) return;
    float x = g_h[i] + b1[i & (F1DIM - 1)];
    g_h[i] = x > 0.f ? x : expm1f(x);
}

// ---------------- layer-2 edge passes ----------------
__global__ void edge_max2(const int* __restrict__ src, const int* __restrict__ dst) {
    int e = blockIdx.x * blockDim.x + threadIdx.x;   // over NE
    if (e >= NE) return;
    int s = src[e], d = dst[e];
    float v = lrelu(g_el2[s] + g_er2[d]);
    atomicMax(&g_m2[d], enc_f(v));
}
__global__ void fix_m2() {
    int i = blockIdx.x * blockDim.x + threadIdx.x;
    if (i >= NN) return;
    float f = dec_f(g_m2[i]);
    g_mf2[i] = isfinite(f) ? f : 0.f;
}
__global__ void edge_sum2(const int* __restrict__ src, const int* __restrict__ dst) {
    int e = blockIdx.x * blockDim.x + threadIdx.x;   // over NE
    if (e >= NE) return;
    int s = src[e], d = dst[e];
    float v = lrelu(g_el2[s] + g_er2[d]);
    float a = expf(v - g_mf2[d]);
    g_a2[e] = a;
    atomicAdd(&g_s2[d], a);
}
__global__ void inv_s2() {
    int i = blockIdx.x * blockDim.x + threadIdx.x;
    if (i >= NN) return;
    float s = g_s2[i];
    g_s2[i] = 1.f / (s > 0.f ? s : 1.f);
}
__global__ void edge_msg2(const int* __restrict__ src, const int* __restrict__ dst,
                          float* __restrict__ out) {
    int idx = blockIdx.x * blockDim.x + threadIdx.x;  // over NE*16
    if (idx >= NE * 16) return;
    int e = idx >> 4, q = idx & 15;
    int s = src[e], d = dst[e];
    float alpha = g_a2[e] * g_s2[d];
    const float4 f = *(const float4*)&g_f2[(size_t)s * ODIM + q * 4];
    red_add_f4(&out[(size_t)d * ODIM + q * 4],
               make_float4(f.x * alpha, f.y * alpha, f.z * alpha, f.w * alpha));
}
__global__ void bias2(float* __restrict__ out, const float* __restrict__ b2) {
    int i = blockIdx.x * blockDim.x + threadIdx.x;   // over NN*ODIM
    if (i >= NN * ODIM) return;
    out[i] += b2[i & (ODIM - 1)];
}

// ---------------- launch ----------------
extern "C" void kernel_launch(void* const* d_in, const int* in_sizes, int n_in,
                              void* d_out, int out_size) {
    const float* feat = (const float*)d_in[0];
    const int*   src  = (const int*)  d_in[1];
    const int*   dst  = (const int*)  d_in[2];
    const float* W1   = (const float*)d_in[3];
    const float* al1  = (const float*)d_in[4];
    const float* ar1  = (const float*)d_in[5];
    const float* b1   = (const float*)d_in[6];
    const float* W2   = (const float*)d_in[7];
    const float* al2  = (const float*)d_in[8];
    const float* ar2  = (const float*)d_in[9];
    const float* b2   = (const float*)d_in[10];
    float* out = (float*)d_out;

    float *pf1, *ph, *pf2;
    cudaGetSymbolAddress((void**)&pf1, g_f1);
    cudaGetSymbolAddress((void**)&ph,  g_h);
    cudaGetSymbolAddress((void**)&pf2, g_f2);

    const int T = 256;
    auto cdiv = [](long long a, long long b) { return (int)((a + b - 1) / b); };

    // Layer 1
    gemm_kernel<64,64,16,4,4><<<dim3(F1DIM/64, cdiv(NN,64)), T>>>(feat, W1, pf1, NN, F1DIM, IN_DIM);
    attn_lr1<<<cdiv(NN*HEADS, T), T>>>(al1, ar1);
    init1<<<cdiv((long long)NN*F1DIM, T), T>>>();
    edge_max1<<<cdiv((long long)NE*HEADS, T), T>>>(src, dst);
    fix_m1<<<cdiv(NN*HEADS, T), T>>>();
    edge_sum1<<<cdiv((long long)NE*HEADS, T), T>>>(src, dst);
    inv_s1<<<cdiv(NN*HEADS, T), T>>>();
    edge_msg1<<<cdiv((long long)NE*64, T), T>>>(src, dst);
    elu_bias1<<<cdiv((long long)NN*F1DIM, T), T>>>(b1);

    // Layer 2
    gemm_kernel<64,64,16,4,4><<<dim3(ODIM/64, cdiv(NN,64)), T>>>(ph, W2, pf2, NN, ODIM, F1DIM);
    attn_lr2<<<cdiv(NN, T), T>>>(al2, ar2);
    init2<<<cdiv((long long)NN*ODIM, T), T>>>(out);
    edge_max2<<<cdiv(NE, T), T>>>(src, dst);
    fix_m2<<<cdiv(NN, T), T>>>();
    edge_sum2<<<cdiv(NE, T), T>>>(src, dst);
    inv_s2<<<cdiv(NN, T), T>>>();
    edge_msg2<<<cdiv((long long)NE*16, T), T>>>(src, dst, out);
    bias2<<<cdiv((long long)NN*ODIM, T), T>>>(out, b2);
}